// round 6
// baseline (speedup 1.0000x reference)
#include <cuda_runtime.h>
#include <cstdint>
#include <math.h>

#define NATOM 50000
#define MNBR  12
#define AFEA  64
#define BFEA  41
#define FAN   169
#define CO    128
#define NROW  600000
#define NT1   4688   // ceil(NROW/128)
#define NT0   391    // ceil(NATOM/128)

// -------- scratch (device globals; heap allocation is forbidden) --------
__device__ float  g_PQ[NATOM * 256];             // [n][0:128]=P(self), [128:256]=Q(nbr)
__device__ float  g_gated[(size_t)NROW * CO];    // 307 MB pre-BN1 activations
__device__ float  g_sumed[NATOM * AFEA];
__device__ double g_s1[CO], g_q1[CO], g_s2[AFEA], g_q2[AFEA];
__device__ float  g_scale1[CO], g_shift1[CO], g_scale2[AFEA], g_shift2[AFEA];

// -------- packed f32x2 helpers (sm_103a) --------
#define FMA2(d, a, b, c) asm("fma.rn.f32x2 %0, %1, %2, %3;" : "=l"(d) : "l"(a), "l"(b), "l"(c))
__device__ __forceinline__ unsigned long long dupf(float x) {
    unsigned long long d; unsigned u = __float_as_uint(x);
    asm("mov.b64 %0, {%1, %2};" : "=l"(d) : "r"(u), "r"(u));
    return d;
}
__device__ __forceinline__ void unpk(float& lo, float& hi, unsigned long long v) {
    unsigned a, b;
    asm("mov.b64 {%0, %1}, %2;" : "=r"(a), "=r"(b) : "l"(v));
    lo = __uint_as_float(a); hi = __uint_as_float(b);
}

__device__ __forceinline__ float sigm(float x) {
    return __fdividef(1.0f, 1.0f + __expf(-x));
}
__device__ __forceinline__ float splus(float x) {
    return fmaxf(x, 0.0f) + __logf(1.0f + __expf(-fabsf(x)));
}

// One k-step: 8 rows x 8 cols per thread, cols paired in f32x2.
// xrow -> 8 consecutive row values (16B aligned), wrow -> 8 consecutive col weights.
__device__ __forceinline__ void mma_step(const float* __restrict__ xrow,
                                         const float* __restrict__ wrow,
                                         unsigned long long acc[8][4]) {
    float4 xa = *(const float4*)(xrow);
    float4 xb = *(const float4*)(xrow + 4);
    unsigned long long w0 = *(const unsigned long long*)(wrow);
    unsigned long long w1 = *(const unsigned long long*)(wrow + 2);
    unsigned long long w2 = *(const unsigned long long*)(wrow + 4);
    unsigned long long w3 = *(const unsigned long long*)(wrow + 6);
    float xr[8] = {xa.x, xa.y, xa.z, xa.w, xb.x, xb.y, xb.z, xb.w};
#pragma unroll
    for (int r = 0; r < 8; ++r) {
        unsigned long long xd = dupf(xr[r]);
        FMA2(acc[r][0], xd, w0, acc[r][0]);
        FMA2(acc[r][1], xd, w1, acc[r][1]);
        FMA2(acc[r][2], xd, w2, acc[r][2]);
        FMA2(acc[r][3], xd, w3, acc[r][3]);
    }
}

// -------- init: zero BN stat accumulators (fresh per graph replay) --------
__global__ void k_init() {
    int i = threadIdx.x;
    if (i < 128)      g_s1[i]       = 0.0;
    else if (i < 256) g_q1[i - 128] = 0.0;
    else if (i < 320) g_s2[i - 256] = 0.0;
    else if (i < 384) g_q2[i - 320] = 0.0;
}

// -------- k0: per-atom projections P,Q --------
__global__ __launch_bounds__(256, 2) void k0_proj(const float* __restrict__ atom,
                                                  const float* __restrict__ W) {
    __shared__ __align__(16) float ws[32 * 128];
    __shared__ __align__(16) float xs[32 * 132];
    const int tid = threadIdx.x;
    const int tc = tid & 15, tr = tid >> 4;
    const int r0 = blockIdx.x * 128;

    for (int h = 0; h < 2; ++h) {          // h=0: W[:, :64] (P), h=1: W[:, 64:128] (Q)
        unsigned long long acc[8][4];
#pragma unroll
        for (int r = 0; r < 8; ++r)
#pragma unroll
            for (int c = 0; c < 4; ++c) acc[r][c] = 0ULL;

        for (int kc = 0; kc < 2; ++kc) {
            __syncthreads();
            for (int i = tid; i < 128 * 32; i += 256) {
                int row = i >> 5, kk = i & 31;
                int gr = r0 + row;
                xs[kk * 132 + row] = (gr < NATOM) ? atom[gr * AFEA + kc * 32 + kk] : 0.0f;
            }
            for (int i = tid; i < 128 * 32; i += 256) {
                int c = i >> 5, kk = i & 31;
                ws[kk * 128 + c] = W[c * FAN + h * 64 + kc * 32 + kk];
            }
            __syncthreads();
#pragma unroll 4
            for (int kk = 0; kk < 32; ++kk)
                mma_step(&xs[kk * 132 + tr * 8], &ws[kk * 128 + tc * 8], acc);
        }
#pragma unroll
        for (int r = 0; r < 8; ++r) {
            int g = r0 + tr * 8 + r;
            if (g < NATOM) {
                float v[8];
#pragma unroll
                for (int c = 0; c < 4; ++c) unpk(v[2 * c], v[2 * c + 1], acc[r][c]);
                float* dst = &g_PQ[(size_t)g * 256 + h * 128 + tc * 8];
                *(float4*)dst       = make_float4(v[0], v[1], v[2], v[3]);
                *(float4*)(dst + 4) = make_float4(v[4], v[5], v[6], v[7]);
            }
        }
    }
}

// -------- k1: edge GEMM + gather epilogue + BN1 stats --------
__global__ __launch_bounds__(256, 2) void k1_main(const float* __restrict__ nbr,
                                                  const int* __restrict__ idx,
                                                  const float* __restrict__ W,
                                                  const float* __restrict__ bvec) {
    __shared__ __align__(16) float ws[41 * 128];
    __shared__ __align__(16) float xs[41 * 132];
    __shared__ int sidx[128];
    __shared__ double red[256];
    const int tid = threadIdx.x;
    const int tc = tid & 15, tr = tid >> 4;
    const int col0 = tc * 8;

    if (tid < 128) { red[tid] = 0.0; red[128 + tid] = 0.0; }
    for (int i = tid; i < 41 * 128; i += 256) {   // edge weights, loaded once
        int c = i / 41, kk = i - c * 41;
        ws[kk * 128 + c] = W[c * FAN + 128 + kk];
    }
    float bv[8];
    {
        float4 b0 = *(const float4*)&bvec[col0];
        float4 b1 = *(const float4*)&bvec[col0 + 4];
        bv[0] = b0.x; bv[1] = b0.y; bv[2] = b0.z; bv[3] = b0.w;
        bv[4] = b1.x; bv[5] = b1.y; bv[6] = b1.z; bv[7] = b1.w;
    }
    float fs[8], fq[8];
#pragma unroll
    for (int c = 0; c < 8; ++c) { fs[c] = 0.0f; fq[c] = 0.0f; }

    for (int t = blockIdx.x; t < NT1; t += gridDim.x) {
        const int r0 = t * 128;
        __syncthreads();
        for (int i = tid; i < 128 * 41; i += 256) {
            int row = i / 41, kk = i - row * 41;
            long gi = (long)r0 * 41 + i;
            xs[kk * 132 + row] = (gi < (long)NROW * 41) ? nbr[gi] : 0.0f;
        }
        if (tid < 128) {
            int gr = r0 + tid;
            sidx[tid] = (gr < NROW) ? idx[gr] : 0;
        }
        __syncthreads();

        unsigned long long acc[8][4];
#pragma unroll
        for (int r = 0; r < 8; ++r)
#pragma unroll
            for (int c = 0; c < 4; ++c) acc[r][c] = 0ULL;
#pragma unroll 4
        for (int kk = 0; kk < 41; ++kk)
            mma_step(&xs[kk * 132 + tr * 8], &ws[kk * 128 + tc * 8], acc);

#pragma unroll
        for (int r = 0; r < 8; ++r) {
            int lr = tr * 8 + r;
            int grow = r0 + lr;
            if (grow < NROW) {
                float v[8];
#pragma unroll
                for (int c = 0; c < 4; ++c) unpk(v[2 * c], v[2 * c + 1], acc[r][c]);
                int n = grow / 12;
                const float* Pp = &g_PQ[(size_t)n * 256 + col0];
                float4 p0 = *(const float4*)Pp;
                float4 p1 = *(const float4*)(Pp + 4);
                const float* Qp = &g_PQ[(size_t)sidx[lr] * 256 + 128 + col0];
                float4 q0 = *(const float4*)Qp;
                float4 q1 = *(const float4*)(Qp + 4);
                v[0] += p0.x + q0.x + bv[0]; v[1] += p0.y + q0.y + bv[1];
                v[2] += p0.z + q0.z + bv[2]; v[3] += p0.w + q0.w + bv[3];
                v[4] += p1.x + q1.x + bv[4]; v[5] += p1.y + q1.y + bv[5];
                v[6] += p1.z + q1.z + bv[6]; v[7] += p1.w + q1.w + bv[7];
                float* dst = &g_gated[(size_t)grow * 128 + col0];
                *(float4*)dst       = make_float4(v[0], v[1], v[2], v[3]);
                *(float4*)(dst + 4) = make_float4(v[4], v[5], v[6], v[7]);
#pragma unroll
                for (int c = 0; c < 8; ++c) { fs[c] += v[c]; fq[c] += v[c] * v[c]; }
            }
        }
    }
    __syncthreads();
#pragma unroll
    for (int c = 0; c < 8; ++c) {
        atomicAdd(&red[col0 + c],       (double)fs[c]);
        atomicAdd(&red[128 + col0 + c], (double)fq[c]);
    }
    __syncthreads();
    if (tid < 128) {
        atomicAdd(&g_s1[tid], red[tid]);
        atomicAdd(&g_q1[tid], red[128 + tid]);
    }
}

// -------- k2: finalize BN1 --------
__global__ void k2_fin(const float* __restrict__ g1, const float* __restrict__ b1) {
    int i = threadIdx.x;
    if (i < CO) {
        double mean = g_s1[i] / (double)NROW;
        double var  = g_q1[i] / (double)NROW - mean * mean;
        float inv = (float)(1.0 / sqrt(var + 1e-5));
        float sc = g1[i] * inv;
        g_scale1[i] = sc;
        g_shift1[i] = b1[i] - (float)mean * sc;
    }
}

// -------- k3: BN1 affine + sigmoid*softplus + neighbor sum + BN2 stats --------
__global__ __launch_bounds__(256) void k3_reduce() {
    __shared__ float sc[128], sh[128];
    __shared__ double rs[64], rq[64];
    const int tid = threadIdx.x;
    if (tid < 128) { sc[tid] = g_scale1[tid]; sh[tid] = g_shift1[tid]; }
    if (tid < 64) { rs[tid] = 0.0; rq[tid] = 0.0; }
    __syncthreads();
    const int l = tid & 31;
    const int gw = (blockIdx.x * blockDim.x + tid) >> 5;
    const int nw = (gridDim.x * blockDim.x) >> 5;
    const float sf0 = sc[l],      hf0 = sh[l];
    const float sf1 = sc[l + 32], hf1 = sh[l + 32];
    const float sc0 = sc[l + 64], hc0 = sh[l + 64];
    const float sc1 = sc[l + 96], hc1 = sh[l + 96];
    float as0 = 0.f, aq0 = 0.f, as1 = 0.f, aq1 = 0.f;
    for (int n = gw; n < NATOM; n += nw) {
        float a0 = 0.f, a1 = 0.f;
        const float* g = &g_gated[(size_t)n * 12 * 128];
#pragma unroll 4
        for (int m = 0; m < 12; ++m) {
            float f0 = g[m * 128 + l]      * sf0 + hf0;
            float f1 = g[m * 128 + l + 32] * sf1 + hf1;
            float c0 = g[m * 128 + l + 64] * sc0 + hc0;
            float c1 = g[m * 128 + l + 96] * sc1 + hc1;
            a0 += sigm(f0) * splus(c0);
            a1 += sigm(f1) * splus(c1);
        }
        g_sumed[n * 64 + l]      = a0;
        g_sumed[n * 64 + l + 32] = a1;
        as0 += a0; aq0 += a0 * a0;
        as1 += a1; aq1 += a1 * a1;
    }
    atomicAdd(&rs[l], (double)as0);      atomicAdd(&rq[l], (double)aq0);
    atomicAdd(&rs[l + 32], (double)as1); atomicAdd(&rq[l + 32], (double)aq1);
    __syncthreads();
    if (tid < 64) { atomicAdd(&g_s2[tid], rs[tid]); atomicAdd(&g_q2[tid], rq[tid]); }
}

// -------- k4: finalize BN2 --------
__global__ void k4_fin(const float* __restrict__ g2, const float* __restrict__ b2) {
    int i = threadIdx.x;
    if (i < AFEA) {
        double mean = g_s2[i] / (double)NATOM;
        double var  = g_q2[i] / (double)NATOM - mean * mean;
        float inv = (float)(1.0 / sqrt(var + 1e-5));
        float sc = g2[i] * inv;
        g_scale2[i] = sc;
        g_shift2[i] = b2[i] - (float)mean * sc;
    }
}

// -------- k5: final softplus --------
__global__ void k5_out(const float* __restrict__ atom, float* __restrict__ out) {
    int i = blockIdx.x * blockDim.x + threadIdx.x;
    if (i < NATOM * AFEA) {
        int a = i & 63;
        float v = atom[i] + g_sumed[i] * g_scale2[a] + g_shift2[a];
        out[i] = splus(v);
    }
}

extern "C" void kernel_launch(void* const* d_in, const int* in_sizes, int n_in,
                              void* d_out, int out_size) {
    const float* atom  = (const float*)d_in[0];
    const float* nbr   = (const float*)d_in[1];
    const int*   idx   = (const int*)d_in[2];
    const float* W     = (const float*)d_in[3];
    const float* bvec  = (const float*)d_in[4];
    const float* bn1g  = (const float*)d_in[5];
    const float* bn1b  = (const float*)d_in[6];
    const float* bn2g  = (const float*)d_in[7];
    const float* bn2b  = (const float*)d_in[8];
    float* out = (float*)d_out;
    (void)in_sizes; (void)n_in; (void)out_size;

    k_init<<<1, 384>>>();
    k0_proj<<<NT0, 256>>>(atom, W);
    k1_main<<<296, 256>>>(nbr, idx, W, bvec);
    k2_fin<<<1, 128>>>(bn1g, bn1b);
    k3_reduce<<<296, 256>>>();
    k4_fin<<<1, 64>>>(bn2g, bn2b);
    k5_out<<<(NATOM * AFEA + 255) / 256, 256>>>(atom, out);
}